// round 4
// baseline (speedup 1.0000x reference)
#include <cuda_runtime.h>
#include <cuda_fp16.h>
#include <cstdint>
#include <cstddef>

// ============================================================
// UUPBitLinear: out = round(clip(x @ (sign(W-mean)*gamma) + bias, -1, 1)*7)/7
//   x: [65536, 512] fp32, W: [512, 512] fp32, bias: [512] fp32
//
// sm_103 (base target, no tcgen05): warp-level mma.sync HMMA path.
// Factor gamma out -> B operand is exact ternary fp16 S^T.
// Split x = hi + lo (fp16 each); products by {-1,0,+1} are exact; two
// fp32-accumulated HMMA passes => ~22-bit effective mantissa, fp32-grade y.
// ============================================================

#define M_TOTAL 65536
#define N_TOTAL 512
#define K_TOTAL 512

#define BM 128
#define BN 128
#define BK 32
#define KB_STEPS (K_TOTAL / BK)   // 16

// dynamic smem layout
//   [0, 512)        : bias tile (float[128])
//   stage s (s=0,1) : base 1024 + s*24576
//     A_hi : +0     (128 rows x 64B)  8KB
//     A_lo : +8192                     8KB
//     B    : +16384                    8KB
#define OFF_BIAS   0
#define STAGE_SZ   24576
#define OFF_AHI(s) (1024 + (s) * STAGE_SZ)
#define OFF_ALO(s) (1024 + (s) * STAGE_SZ + 8192)
#define OFF_BT(s)  (1024 + (s) * STAGE_SZ + 16384)
#define SMEM_TOTAL (1024 + 2 * STAGE_SZ)   // 50176 bytes

// ---- device scratch (allocation-free) ----
__device__ float  g_part_sum[512];
__device__ float  g_part_abs[512];
__device__ float  g_mean;
__device__ float  g_gamma;
__device__ __half g_ST[N_TOTAL * K_TOTAL];   // S^T: [N][K] fp16 ternary

// ---- helpers ----
__device__ __forceinline__ uint32_t smem_u32(const void* p) {
    uint32_t a;
    asm("{ .reg .u64 t; cvta.to.shared.u64 t, %1; cvt.u32.u64 %0, t; }"
        : "=r"(a) : "l"(p));
    return a;
}

// rows are 64B (32 halfs). chunk = 16B unit (0..3). Swizzle chunk by
// (row>>1)&3 so 8 consecutive rows of one ldmatrix hit 8 distinct 16B
// bank-groups (conflict-free).
__device__ __forceinline__ uint32_t sw_off(int row, int chunk) {
    return (uint32_t)(row * 64 + (((chunk ^ ((row >> 1) & 3)) & 3) << 4));
}

#define LDSM_X4(r0, r1, r2, r3, addr)                                      \
    asm volatile("ldmatrix.sync.aligned.m8n8.x4.shared.b16 "               \
                 "{%0,%1,%2,%3}, [%4];"                                    \
                 : "=r"(r0), "=r"(r1), "=r"(r2), "=r"(r3) : "r"(addr))

#define MMA16816(d, a0, a1, a2, a3, b0, b1)                                \
    asm volatile("mma.sync.aligned.m16n8k16.row.col.f32.f16.f16.f32 "      \
                 "{%0,%1,%2,%3}, {%4,%5,%6,%7}, {%8,%9}, {%0,%1,%2,%3};"   \
                 : "+f"((d)[0]), "+f"((d)[1]), "+f"((d)[2]), "+f"((d)[3])  \
                 : "r"(a0), "r"(a1), "r"(a2), "r"(a3), "r"(b0), "r"(b1))

__device__ __forceinline__ uint32_t pack_h2(__half a, __half b) {
    __half2 h = __halves2half2(a, b);
    return *reinterpret_cast<uint32_t*>(&h);
}

__device__ __forceinline__ float quantize(float y) {
    y = fminf(fmaxf(y, -1.0f), 1.0f);
    return rintf(y * 7.0f) * (1.0f / 7.0f);   // round-half-even == jnp.round
}

// ---- prep kernel 1: deterministic per-row reduction of W ----
__global__ void reduce_rows(const float* __restrict__ w) {
    __shared__ float ss[256], sa[256];
    int r = blockIdx.x, t = threadIdx.x;
    float v0 = w[r * 512 + t];
    float v1 = w[r * 512 + t + 256];
    ss[t] = v0 + v1;
    sa[t] = fabsf(v0) + fabsf(v1);
    __syncthreads();
    #pragma unroll
    for (int o = 128; o > 0; o >>= 1) {
        if (t < o) { ss[t] += ss[t + o]; sa[t] += sa[t + o]; }
        __syncthreads();
    }
    if (t == 0) { g_part_sum[r] = ss[0]; g_part_abs[r] = sa[0]; }
}

// ---- prep kernel 2: final deterministic reduce -> mean, gamma ----
__global__ void reduce_final() {
    __shared__ float ss[256], sa[256];
    int t = threadIdx.x;
    ss[t] = g_part_sum[t] + g_part_sum[t + 256];
    sa[t] = g_part_abs[t] + g_part_abs[t + 256];
    __syncthreads();
    #pragma unroll
    for (int o = 128; o > 0; o >>= 1) {
        if (t < o) { ss[t] += ss[t + o]; sa[t] += sa[t + o]; }
        __syncthreads();
    }
    if (t == 0) {
        g_mean  = ss[0] * (1.0f / 262144.0f);
        g_gamma = sa[0] * (1.0f / 262144.0f);
    }
}

// ---- prep kernel 3: pack S^T[n][k] = sign(W[k][n] - mean) as fp16 ----
__global__ void pack_signs(const float* __restrict__ w) {
    int n = blockIdx.x;      // 512 blocks
    int k = threadIdx.x;     // 512 threads
    float d = w[k * 512 + n] - g_mean;
    float s = (d > 0.0f) ? 1.0f : ((d < 0.0f) ? -1.0f : 0.0f);
    g_ST[n * 512 + k] = __float2half(s);
}

// ---- main GEMM ----
__global__ void __launch_bounds__(256)
bitlinear_gemm(const float* __restrict__ x, const float* __restrict__ bias,
               float* __restrict__ out) {
    extern __shared__ unsigned char smem[];
    const uint32_t sb = smem_u32(smem);
    const int tid = threadIdx.x;
    const int wid = tid >> 5;
    const int lid = tid & 31;
    const int warp_m = wid & 3;       // 4 warps along M (32 rows each)
    const int warp_n = wid >> 2;      // 2 warps along N (64 cols each)
    const int m0 = blockIdx.x * BM;
    const int n0 = blockIdx.y * BN;

    if (tid < BN) {
        reinterpret_cast<float*>(smem + OFF_BIAS)[tid] = bias[n0 + tid];
    }

    // staging roles: thread -> (row = tid>>1, half kh = tid&1 covering 16 k)
    const int srow = tid >> 1;
    const int kh   = tid & 1;
    const float* aptr = x + (size_t)(m0 + srow) * K_TOTAL + kh * 16;
    const char*  bptr = reinterpret_cast<const char*>(g_ST)
                        + (size_t)(n0 + srow) * (K_TOTAL * 2) + kh * 32;

    float  fa[16];
    uint4  bv[2];

    // ---- prefetch + stage kb = 0 ----
    {
        const float4* ap = reinterpret_cast<const float4*>(aptr);
        float4 f0 = ap[0], f1 = ap[1], f2 = ap[2], f3 = ap[3];
        fa[0]=f0.x; fa[1]=f0.y; fa[2]=f0.z; fa[3]=f0.w;
        fa[4]=f1.x; fa[5]=f1.y; fa[6]=f1.z; fa[7]=f1.w;
        fa[8]=f2.x; fa[9]=f2.y; fa[10]=f2.z; fa[11]=f2.w;
        fa[12]=f3.x; fa[13]=f3.y; fa[14]=f3.z; fa[15]=f3.w;
        bv[0] = *reinterpret_cast<const uint4*>(bptr);
        bv[1] = *reinterpret_cast<const uint4*>(bptr + 16);
    }
    {
        uint32_t hi[8], lo[8];
        #pragma unroll
        for (int i = 0; i < 8; i++) {
            float a = fa[2*i], b = fa[2*i+1];
            __half ha = __float2half_rn(a), hb = __float2half_rn(b);
            __half la = __float2half_rn(a - __half2float(ha));
            __half lb = __float2half_rn(b - __half2float(hb));
            hi[i] = pack_h2(ha, hb);
            lo[i] = pack_h2(la, lb);
        }
        #pragma unroll
        for (int j = 0; j < 2; j++) {
            uint32_t o = sw_off(srow, kh * 2 + j);
            *reinterpret_cast<uint4*>(smem + OFF_AHI(0) + o) =
                make_uint4(hi[4*j], hi[4*j+1], hi[4*j+2], hi[4*j+3]);
            *reinterpret_cast<uint4*>(smem + OFF_ALO(0) + o) =
                make_uint4(lo[4*j], lo[4*j+1], lo[4*j+2], lo[4*j+3]);
            *reinterpret_cast<uint4*>(smem + OFF_BT(0) + o) = bv[j];
        }
    }
    __syncthreads();

    float acc[2][8][4];
    #pragma unroll
    for (int i = 0; i < 2; i++)
        #pragma unroll
        for (int j = 0; j < 8; j++)
            #pragma unroll
            for (int c = 0; c < 4; c++) acc[i][j][c] = 0.0f;

    for (int kb = 0; kb < KB_STEPS; kb++) {
        // prefetch next stage into registers
        if (kb < KB_STEPS - 1) {
            const float4* ap = reinterpret_cast<const float4*>(aptr + (kb + 1) * BK);
            float4 f0 = ap[0], f1 = ap[1], f2 = ap[2], f3 = ap[3];
            fa[0]=f0.x; fa[1]=f0.y; fa[2]=f0.z; fa[3]=f0.w;
            fa[4]=f1.x; fa[5]=f1.y; fa[6]=f1.z; fa[7]=f1.w;
            fa[8]=f2.x; fa[9]=f2.y; fa[10]=f2.z; fa[11]=f2.w;
            fa[12]=f3.x; fa[13]=f3.y; fa[14]=f3.z; fa[15]=f3.w;
            bv[0] = *reinterpret_cast<const uint4*>(bptr + (kb + 1) * 64);
            bv[1] = *reinterpret_cast<const uint4*>(bptr + (kb + 1) * 64 + 16);
        }

        // MMA over current stage
        const int s = kb & 1;
        const uint32_t ahi = sb + OFF_AHI(s);
        const uint32_t alo = sb + OFF_ALO(s);
        const uint32_t bsm = sb + OFF_BT(s);
        const int fr  = lid & 15;     // ldmatrix row within 16
        const int fch = lid >> 4;     // ldmatrix chunk select (k half)

        #pragma unroll
        for (int ks = 0; ks < 2; ks++) {
            uint32_t a_hi[2][4], a_lo[2][4], bq[4][4];
            #pragma unroll
            for (int mt = 0; mt < 2; mt++) {
                int row = warp_m * 32 + mt * 16 + fr;
                uint32_t o = sw_off(row, ks * 2 + fch);
                LDSM_X4(a_hi[mt][0], a_hi[mt][1], a_hi[mt][2], a_hi[mt][3], ahi + o);
                LDSM_X4(a_lo[mt][0], a_lo[mt][1], a_lo[mt][2], a_lo[mt][3], alo + o);
            }
            #pragma unroll
            for (int p = 0; p < 4; p++) {   // 2 n-tiles per ldmatrix.x4
                int row = warp_n * 64 + p * 16 + fr;
                uint32_t o = sw_off(row, ks * 2 + fch);
                LDSM_X4(bq[p][0], bq[p][1], bq[p][2], bq[p][3], bsm + o);
            }
            #pragma unroll
            for (int mt = 0; mt < 2; mt++) {
                #pragma unroll
                for (int nt = 0; nt < 8; nt++) {
                    // ntile nt: pair p = nt>>1, regs {q0,q2} (even) / {q1,q3} (odd)
                    uint32_t b0 = bq[nt >> 1][nt & 1];
                    uint32_t b1 = bq[nt >> 1][2 + (nt & 1)];
                    MMA16816(acc[mt][nt], a_hi[mt][0], a_hi[mt][1], a_hi[mt][2], a_hi[mt][3], b0, b1);
                    MMA16816(acc[mt][nt], a_lo[mt][0], a_lo[mt][1], a_lo[mt][2], a_lo[mt][3], b0, b1);
                }
            }
        }
        __syncthreads();

        // stage next buffer
        if (kb < KB_STEPS - 1) {
            uint32_t hi[8], lo[8];
            #pragma unroll
            for (int i = 0; i < 8; i++) {
                float a = fa[2*i], b = fa[2*i+1];
                __half ha = __float2half_rn(a), hb = __float2half_rn(b);
                __half la = __float2half_rn(a - __half2float(ha));
                __half lb = __float2half_rn(b - __half2float(hb));
                hi[i] = pack_h2(ha, hb);
                lo[i] = pack_h2(la, lb);
            }
            const int ns = (kb + 1) & 1;
            #pragma unroll
            for (int j = 0; j < 2; j++) {
                uint32_t o = sw_off(srow, kh * 2 + j);
                *reinterpret_cast<uint4*>(smem + OFF_AHI(ns) + o) =
                    make_uint4(hi[4*j], hi[4*j+1], hi[4*j+2], hi[4*j+3]);
                *reinterpret_cast<uint4*>(smem + OFF_ALO(ns) + o) =
                    make_uint4(lo[4*j], lo[4*j+1], lo[4*j+2], lo[4*j+3]);
                *reinterpret_cast<uint4*>(smem + OFF_BT(ns) + o) = bv[j];
            }
            __syncthreads();
        }
    }

    // ---- epilogue: scale by gamma, add bias, quantize, store ----
    const float gamma = g_gamma;
    const float* bias_s = reinterpret_cast<const float*>(smem + OFF_BIAS);
    #pragma unroll
    for (int mt = 0; mt < 2; mt++) {
        int row0 = m0 + warp_m * 32 + mt * 16 + (lid >> 2);
        #pragma unroll
        for (int nt = 0; nt < 8; nt++) {
            int coln = warp_n * 64 + nt * 8 + (lid & 3) * 2;
            float b0 = bias_s[coln], b1 = bias_s[coln + 1];
            float2 v0, v1;
            v0.x = quantize(acc[mt][nt][0] * gamma + b0);
            v0.y = quantize(acc[mt][nt][1] * gamma + b1);
            v1.x = quantize(acc[mt][nt][2] * gamma + b0);
            v1.y = quantize(acc[mt][nt][3] * gamma + b1);
            *reinterpret_cast<float2*>(out + (size_t)row0 * N_TOTAL + n0 + coln) = v0;
            *reinterpret_cast<float2*>(out + (size_t)(row0 + 8) * N_TOTAL + n0 + coln) = v1;
        }
    }
}

// ---- harness entry ----
extern "C" void kernel_launch(void* const* d_in, const int* in_sizes, int n_in,
                              void* d_out, int out_size) {
    const float* x    = (const float*)d_in[0];
    const float* w    = (const float*)d_in[1];
    const float* bias = (const float*)d_in[2];
    float* out = (float*)d_out;

    static bool attr_set = false;
    cudaFuncSetAttribute(bitlinear_gemm,
                         cudaFuncAttributeMaxDynamicSharedMemorySize, SMEM_TOTAL);
    (void)attr_set;

    reduce_rows<<<512, 256>>>(w);
    reduce_final<<<1, 256>>>();
    pack_signs<<<512, 512>>>(w);

    dim3 grid(M_TOTAL / BM, N_TOTAL / BN);   // (512, 4)
    bitlinear_gemm<<<grid, 256, SMEM_TOTAL>>>(x, bias, out);
}

// round 5
// speedup vs baseline: 1.1231x; 1.1231x over previous
#include <cuda_runtime.h>
#include <cuda_fp16.h>
#include <cstdint>
#include <cstddef>

// ============================================================
// UUPBitLinear: out = round(clip(x @ (sign(W-mean)*gamma) + bias, -1, 1)*7)/7
//   x: [65536, 512] fp32, W: [512, 512] fp32, bias: [512] fp32
//
// HMMA mma.sync path (sm_103 base target). gamma factored out -> B operand is
// exact ternary fp16 S^T. x pre-split into hi/lo fp16 by a prep kernel; the
// GEMM is a pure cp.async 4-stage pipelined fp16 MMA with fp32 accumulate.
// ============================================================

#define M_TOTAL 65536
#define N_TOTAL 512
#define K_TOTAL 512

#define BM 128
#define BN 128
#define BK 32
#define KB_STEPS (K_TOTAL / BK)   // 16
#define STAGES 4

// dynamic smem: [0,512) bias; stages at 1024 + s*24576
#define OFF_BIAS   0
#define STAGE_SZ   24576
#define OFF_AHI(s) (1024 + (s) * STAGE_SZ)
#define OFF_ALO(s) (1024 + (s) * STAGE_SZ + 8192)
#define OFF_BT(s)  (1024 + (s) * STAGE_SZ + 16384)
#define SMEM_TOTAL (1024 + STAGES * STAGE_SZ)   // 99328 -> 2 CTAs/SM

// ---- device scratch (allocation-free) ----
__device__ float  g_part_sum[512];
__device__ float  g_part_abs[512];
__device__ float  g_mean;
__device__ float  g_gamma;
__device__ __half g_ST[N_TOTAL * K_TOTAL];            // S^T: [N][K] ternary fp16
__device__ __half g_xhi[(size_t)M_TOTAL * K_TOTAL];   // 64 MB
__device__ __half g_xlo[(size_t)M_TOTAL * K_TOTAL];   // 64 MB

// ---- helpers ----
__device__ __forceinline__ uint32_t smem_u32(const void* p) {
    uint32_t a;
    asm("{ .reg .u64 t; cvta.to.shared.u64 t, %1; cvt.u32.u64 %0, t; }"
        : "=r"(a) : "l"(p));
    return a;
}

// rows are 64B (32 halfs); chunk = 16B unit (0..3), swizzled so ldmatrix's
// 8-row groups hit distinct banks (validated in R3).
__device__ __forceinline__ uint32_t sw_off(int row, int chunk) {
    return (uint32_t)(row * 64 + (((chunk ^ ((row >> 1) & 3)) & 3) << 4));
}

#define LDSM_X4(r0, r1, r2, r3, addr)                                      \
    asm volatile("ldmatrix.sync.aligned.m8n8.x4.shared.b16 "               \
                 "{%0,%1,%2,%3}, [%4];"                                    \
                 : "=r"(r0), "=r"(r1), "=r"(r2), "=r"(r3) : "r"(addr))

#define MMA16816(d, a0, a1, a2, a3, b0, b1)                                \
    asm volatile("mma.sync.aligned.m16n8k16.row.col.f32.f16.f16.f32 "      \
                 "{%0,%1,%2,%3}, {%4,%5,%6,%7}, {%8,%9}, {%0,%1,%2,%3};"   \
                 : "+f"((d)[0]), "+f"((d)[1]), "+f"((d)[2]), "+f"((d)[3])  \
                 : "r"(a0), "r"(a1), "r"(a2), "r"(a3), "r"(b0), "r"(b1))

#define CP16(smaddr, gptr)                                                 \
    asm volatile("cp.async.cg.shared.global [%0], [%1], 16;"               \
                 :: "r"(smaddr), "l"(__cvta_generic_to_global(gptr)) : "memory")

#define CP_COMMIT() asm volatile("cp.async.commit_group;" ::: "memory")
#define CP_WAIT2()  asm volatile("cp.async.wait_group 2;" ::: "memory")

__device__ __forceinline__ uint32_t pack_h2(__half a, __half b) {
    __half2 h = __halves2half2(a, b);
    return *reinterpret_cast<uint32_t*>(&h);
}

__device__ __forceinline__ float quantize(float y) {
    y = fminf(fmaxf(y, -1.0f), 1.0f);
    return rintf(y * 7.0f) * (1.0f / 7.0f);   // round-half-even == jnp.round
}

// ---- prep 1: deterministic per-row reduction of W ----
__global__ void reduce_rows(const float* __restrict__ w) {
    __shared__ float ss[256], sa[256];
    int r = blockIdx.x, t = threadIdx.x;
    float v0 = w[r * 512 + t];
    float v1 = w[r * 512 + t + 256];
    ss[t] = v0 + v1;
    sa[t] = fabsf(v0) + fabsf(v1);
    __syncthreads();
    #pragma unroll
    for (int o = 128; o > 0; o >>= 1) {
        if (t < o) { ss[t] += ss[t + o]; sa[t] += sa[t + o]; }
        __syncthreads();
    }
    if (t == 0) { g_part_sum[r] = ss[0]; g_part_abs[r] = sa[0]; }
}

// ---- prep 2: final deterministic reduce -> mean, gamma ----
__global__ void reduce_final() {
    __shared__ float ss[256], sa[256];
    int t = threadIdx.x;
    ss[t] = g_part_sum[t] + g_part_sum[t + 256];
    sa[t] = g_part_abs[t] + g_part_abs[t + 256];
    __syncthreads();
    #pragma unroll
    for (int o = 128; o > 0; o >>= 1) {
        if (t < o) { ss[t] += ss[t + o]; sa[t] += sa[t + o]; }
        __syncthreads();
    }
    if (t == 0) {
        g_mean  = ss[0] * (1.0f / 262144.0f);
        g_gamma = sa[0] * (1.0f / 262144.0f);
    }
}

// ---- prep 3: pack S^T[n][k] = sign(W[k][n] - mean) as fp16 ----
__global__ void pack_signs(const float* __restrict__ w) {
    int n = blockIdx.x;
    int k = threadIdx.x;
    float d = w[k * 512 + n] - g_mean;
    float s = (d > 0.0f) ? 1.0f : ((d < 0.0f) ? -1.0f : 0.0f);
    g_ST[n * 512 + k] = __float2half(s);
}

// ---- prep 4: split x into fp16 hi/lo (exact 2-term decomposition) ----
__global__ void __launch_bounds__(256)
split_x(const float* __restrict__ x) {
    size_t i = ((size_t)blockIdx.x * 256 + threadIdx.x) * 8;
    float4 a = *reinterpret_cast<const float4*>(x + i);
    float4 b = *reinterpret_cast<const float4*>(x + i + 4);
    float f[8] = {a.x, a.y, a.z, a.w, b.x, b.y, b.z, b.w};
    uint32_t hi[4], lo[4];
    #pragma unroll
    for (int j = 0; j < 4; j++) {
        float u = f[2 * j], v = f[2 * j + 1];
        __half hu = __float2half_rn(u), hv = __float2half_rn(v);
        __half lu = __float2half_rn(u - __half2float(hu));
        __half lv = __float2half_rn(v - __half2float(hv));
        hi[j] = pack_h2(hu, hv);
        lo[j] = pack_h2(lu, lv);
    }
    *reinterpret_cast<uint4*>(g_xhi + i) = make_uint4(hi[0], hi[1], hi[2], hi[3]);
    *reinterpret_cast<uint4*>(g_xlo + i) = make_uint4(lo[0], lo[1], lo[2], lo[3]);
}

// ---- main GEMM: 4-stage cp.async pipeline, fp16 HMMA, fp32 accumulate ----
__global__ void __launch_bounds__(256, 2)
bitlinear_gemm(const float* __restrict__ bias, float* __restrict__ out) {
    extern __shared__ unsigned char smem[];
    const uint32_t sb = smem_u32(smem);
    const int tid = threadIdx.x;
    const int wid = tid >> 5;
    const int lid = tid & 31;
    const int warp_m = wid & 3;       // 4 warps along M (32 rows each)
    const int warp_n = wid >> 2;      // 2 warps along N (64 cols each)
    const int n0 = blockIdx.x * BN;   // grid.x = 4  (n fastest -> L2 reuse of x)
    const int m0 = blockIdx.y * BM;   // grid.y = 512

    if (tid < BN) {
        reinterpret_cast<float*>(smem + OFF_BIAS)[tid] = bias[n0 + tid];
    }

    // staging roles: thread -> (row = tid>>1, chunk-pair cp = tid&1)
    const int srow = tid >> 1;
    const int cp   = tid & 1;
    const __half* ah_base = g_xhi + (size_t)(m0 + srow) * K_TOTAL + cp * 16;
    const __half* al_base = g_xlo + (size_t)(m0 + srow) * K_TOTAL + cp * 16;
    const __half* b_base  = g_ST  + (size_t)(n0 + srow) * K_TOTAL + cp * 16;
    const uint32_t sw0 = sw_off(srow, cp * 2 + 0);
    const uint32_t sw1 = sw_off(srow, cp * 2 + 1);

    auto issue_stage = [&](int kb) {
        if (kb < KB_STEPS) {
            const int buf = kb & (STAGES - 1);
            const __half* ah = ah_base + kb * BK;
            const __half* al = al_base + kb * BK;
            const __half* bp = b_base  + kb * BK;
            CP16(sb + OFF_AHI(buf) + sw0, ah);
            CP16(sb + OFF_AHI(buf) + sw1, ah + 8);
            CP16(sb + OFF_ALO(buf) + sw0, al);
            CP16(sb + OFF_ALO(buf) + sw1, al + 8);
            CP16(sb + OFF_BT(buf)  + sw0, bp);
            CP16(sb + OFF_BT(buf)  + sw1, bp + 8);
        }
        CP_COMMIT();
    };

    issue_stage(0);
    issue_stage(1);
    issue_stage(2);

    float acc[2][8][4];
    #pragma unroll
    for (int i = 0; i < 2; i++)
        #pragma unroll
        for (int j = 0; j < 8; j++)
            #pragma unroll
            for (int c = 0; c < 4; c++) acc[i][j][c] = 0.0f;

    const int fr  = lid & 15;     // ldmatrix row within 16
    const int fch = lid >> 4;     // k-half select

    for (int kb = 0; kb < KB_STEPS; kb++) {
        CP_WAIT2();               // stage kb complete (3 groups in flight)
        __syncthreads();          // visible to all; stage kb-1 fully consumed
        issue_stage(kb + 3);      // refill buf (kb-1)&3 — safe post-barrier

        const int buf = kb & (STAGES - 1);
        const uint32_t ahi = sb + OFF_AHI(buf);
        const uint32_t alo = sb + OFF_ALO(buf);
        const uint32_t bsm = sb + OFF_BT(buf);

        #pragma unroll
        for (int ks = 0; ks < 2; ks++) {
            uint32_t a_hi[2][4], a_lo[2][4], bq[4][4];
            #pragma unroll
            for (int mt = 0; mt < 2; mt++) {
                int row = warp_m * 32 + mt * 16 + fr;
                uint32_t o = sw_off(row, ks * 2 + fch);
                LDSM_X4(a_hi[mt][0], a_hi[mt][1], a_hi[mt][2], a_hi[mt][3], ahi + o);
                LDSM_X4(a_lo[mt][0], a_lo[mt][1], a_lo[mt][2], a_lo[mt][3], alo + o);
            }
            #pragma unroll
            for (int p = 0; p < 4; p++) {
                int row = warp_n * 64 + p * 16 + fr;
                uint32_t o = sw_off(row, ks * 2 + fch);
                LDSM_X4(bq[p][0], bq[p][1], bq[p][2], bq[p][3], bsm + o);
            }
            #pragma unroll
            for (int mt = 0; mt < 2; mt++) {
                #pragma unroll
                for (int nt = 0; nt < 8; nt++) {
                    uint32_t b0 = bq[nt >> 1][nt & 1];
                    uint32_t b1 = bq[nt >> 1][2 + (nt & 1)];
                    MMA16816(acc[mt][nt], a_hi[mt][0], a_hi[mt][1], a_hi[mt][2], a_hi[mt][3], b0, b1);
                    MMA16816(acc[mt][nt], a_lo[mt][0], a_lo[mt][1], a_lo[mt][2], a_lo[mt][3], b0, b1);
                }
            }
        }
    }

    // ---- epilogue: scale by gamma, add bias, quantize, store ----
    const float gamma = g_gamma;
    const float* bias_s = reinterpret_cast<const float*>(smem + OFF_BIAS);
    #pragma unroll
    for (int mt = 0; mt < 2; mt++) {
        int row0 = m0 + warp_m * 32 + mt * 16 + (lid >> 2);
        #pragma unroll
        for (int nt = 0; nt < 8; nt++) {
            int coln = warp_n * 64 + nt * 8 + (lid & 3) * 2;
            float b0 = bias_s[coln], b1 = bias_s[coln + 1];
            float2 v0, v1;
            v0.x = quantize(acc[mt][nt][0] * gamma + b0);
            v0.y = quantize(acc[mt][nt][1] * gamma + b1);
            v1.x = quantize(acc[mt][nt][2] * gamma + b0);
            v1.y = quantize(acc[mt][nt][3] * gamma + b1);
            *reinterpret_cast<float2*>(out + (size_t)row0 * N_TOTAL + n0 + coln) = v0;
            *reinterpret_cast<float2*>(out + (size_t)(row0 + 8) * N_TOTAL + n0 + coln) = v1;
        }
    }
}

// ---- harness entry ----
extern "C" void kernel_launch(void* const* d_in, const int* in_sizes, int n_in,
                              void* d_out, int out_size) {
    const float* x    = (const float*)d_in[0];
    const float* w    = (const float*)d_in[1];
    const float* bias = (const float*)d_in[2];
    float* out = (float*)d_out;

    cudaFuncSetAttribute(bitlinear_gemm,
                         cudaFuncAttributeMaxDynamicSharedMemorySize, SMEM_TOTAL);

    reduce_rows<<<512, 256>>>(w);
    reduce_final<<<1, 256>>>();
    pack_signs<<<512, 512>>>(w);
    split_x<<<(M_TOTAL * K_TOTAL) / (8 * 256), 256>>>(x);

    dim3 grid(N_TOTAL / BN, M_TOTAL / BM);   // (4, 512): n fastest
    bitlinear_gemm<<<grid, 256, SMEM_TOTAL>>>(bias, out);
}

// round 6
// speedup vs baseline: 1.2017x; 1.0699x over previous
#include <cuda_runtime.h>
#include <cuda_fp16.h>
#include <cstdint>
#include <cstddef>

// ============================================================
// UUPBitLinear: out = round(clip(x @ (sign(W-mean)*gamma) + bias, -1, 1)*7)/7
//   x: [65536, 512] fp32, W: [512, 512] fp32, bias: [512] fp32
//
// HMMA mma.sync path (sm_103 base target). gamma factored out -> B operand is
// exact ternary fp16 S^T. x pre-split into hi/lo fp16 by a prep kernel; GEMM
// is a 3-stage cp.async pipelined fp16 MMA, fp32 accumulate.
// R5: BN=64 / warp tile 32x32 -> 32 accum regs/thread, 3 CTAs/SM (24 warps).
// ============================================================

#define M_TOTAL 65536
#define N_TOTAL 512
#define K_TOTAL 512

#define BM 128
#define BN 64
#define BK 32
#define KB_STEPS (K_TOTAL / BK)   // 16
#define STAGES 3

// dynamic smem: [0,256) bias; stages at 1024 + s*20480
//   A_hi: 128 rows x 64B = 8192 ; A_lo: 8192 ; B: 64 rows x 64B = 4096
#define OFF_BIAS   0
#define STAGE_SZ   20480
#define OFF_AHI(s) (1024 + (s) * STAGE_SZ)
#define OFF_ALO(s) (1024 + (s) * STAGE_SZ + 8192)
#define OFF_BT(s)  (1024 + (s) * STAGE_SZ + 16384)
#define SMEM_TOTAL (1024 + STAGES * STAGE_SZ)   // 62464 -> 3 CTAs/SM

// ---- device scratch (allocation-free) ----
__device__ float  g_part_sum[512];
__device__ float  g_part_abs[512];
__device__ float  g_mean;
__device__ float  g_gamma;
__device__ __half g_ST[N_TOTAL * K_TOTAL];            // S^T: [N][K] ternary fp16
__device__ __half g_xhi[(size_t)M_TOTAL * K_TOTAL];   // 64 MB
__device__ __half g_xlo[(size_t)M_TOTAL * K_TOTAL];   // 64 MB

// ---- helpers ----
__device__ __forceinline__ uint32_t smem_u32(const void* p) {
    uint32_t a;
    asm("{ .reg .u64 t; cvta.to.shared.u64 t, %1; cvt.u32.u64 %0, t; }"
        : "=r"(a) : "l"(p));
    return a;
}

// rows are 64B (32 halfs); chunk = 16B unit (0..3), swizzled so ldmatrix's
// 8-row groups hit distinct banks (validated in R3/R4).
__device__ __forceinline__ uint32_t sw_off(int row, int chunk) {
    return (uint32_t)(row * 64 + (((chunk ^ ((row >> 1) & 3)) & 3) << 4));
}

#define LDSM_X4(r0, r1, r2, r3, addr)                                      \
    asm volatile("ldmatrix.sync.aligned.m8n8.x4.shared.b16 "               \
                 "{%0,%1,%2,%3}, [%4];"                                    \
                 : "=r"(r0), "=r"(r1), "=r"(r2), "=r"(r3) : "r"(addr))

#define MMA16816(d, a0, a1, a2, a3, b0, b1)                                \
    asm volatile("mma.sync.aligned.m16n8k16.row.col.f32.f16.f16.f32 "      \
                 "{%0,%1,%2,%3}, {%4,%5,%6,%7}, {%8,%9}, {%0,%1,%2,%3};"   \
                 : "+f"((d)[0]), "+f"((d)[1]), "+f"((d)[2]), "+f"((d)[3])  \
                 : "r"(a0), "r"(a1), "r"(a2), "r"(a3), "r"(b0), "r"(b1))

#define CP16(smaddr, gptr)                                                 \
    asm volatile("cp.async.cg.shared.global [%0], [%1], 16;"               \
                 :: "r"(smaddr), "l"(__cvta_generic_to_global(gptr)) : "memory")

#define CP_COMMIT() asm volatile("cp.async.commit_group;" ::: "memory")
#define CP_WAIT1()  asm volatile("cp.async.wait_group 1;" ::: "memory")

__device__ __forceinline__ uint32_t pack_h2(__half a, __half b) {
    __half2 h = __halves2half2(a, b);
    return *reinterpret_cast<uint32_t*>(&h);
}

__device__ __forceinline__ float quantize(float y) {
    y = fminf(fmaxf(y, -1.0f), 1.0f);
    return rintf(y * 7.0f) * (1.0f / 7.0f);   // round-half-even == jnp.round
}

// ---- prep 1: deterministic per-row reduction of W ----
__global__ void reduce_rows(const float* __restrict__ w) {
    __shared__ float ss[256], sa[256];
    int r = blockIdx.x, t = threadIdx.x;
    float v0 = w[r * 512 + t];
    float v1 = w[r * 512 + t + 256];
    ss[t] = v0 + v1;
    sa[t] = fabsf(v0) + fabsf(v1);
    __syncthreads();
    #pragma unroll
    for (int o = 128; o > 0; o >>= 1) {
        if (t < o) { ss[t] += ss[t + o]; sa[t] += sa[t + o]; }
        __syncthreads();
    }
    if (t == 0) { g_part_sum[r] = ss[0]; g_part_abs[r] = sa[0]; }
}

// ---- prep 2: final deterministic reduce -> mean, gamma ----
__global__ void reduce_final() {
    __shared__ float ss[256], sa[256];
    int t = threadIdx.x;
    ss[t] = g_part_sum[t] + g_part_sum[t + 256];
    sa[t] = g_part_abs[t] + g_part_abs[t + 256];
    __syncthreads();
    #pragma unroll
    for (int o = 128; o > 0; o >>= 1) {
        if (t < o) { ss[t] += ss[t + o]; sa[t] += sa[t + o]; }
        __syncthreads();
    }
    if (t == 0) {
        g_mean  = ss[0] * (1.0f / 262144.0f);
        g_gamma = sa[0] * (1.0f / 262144.0f);
    }
}

// ---- prep 3: pack S^T[n][k] = sign(W[k][n] - mean) as fp16 ----
__global__ void pack_signs(const float* __restrict__ w) {
    int n = blockIdx.x;
    int k = threadIdx.x;
    float d = w[k * 512 + n] - g_mean;
    float s = (d > 0.0f) ? 1.0f : ((d < 0.0f) ? -1.0f : 0.0f);
    g_ST[n * 512 + k] = __float2half(s);
}

// ---- prep 4: split x into fp16 hi/lo (exact 2-term decomposition) ----
__global__ void __launch_bounds__(256)
split_x(const float* __restrict__ x) {
    size_t i = ((size_t)blockIdx.x * 256 + threadIdx.x) * 8;
    float4 a = *reinterpret_cast<const float4*>(x + i);
    float4 b = *reinterpret_cast<const float4*>(x + i + 4);
    float f[8] = {a.x, a.y, a.z, a.w, b.x, b.y, b.z, b.w};
    uint32_t hi[4], lo[4];
    #pragma unroll
    for (int j = 0; j < 4; j++) {
        float u = f[2 * j], v = f[2 * j + 1];
        __half hu = __float2half_rn(u), hv = __float2half_rn(v);
        __half lu = __float2half_rn(u - __half2float(hu));
        __half lv = __float2half_rn(v - __half2float(hv));
        hi[j] = pack_h2(hu, hv);
        lo[j] = pack_h2(lu, lv);
    }
    *reinterpret_cast<uint4*>(g_xhi + i) = make_uint4(hi[0], hi[1], hi[2], hi[3]);
    *reinterpret_cast<uint4*>(g_xlo + i) = make_uint4(lo[0], lo[1], lo[2], lo[3]);
}

// ---- main GEMM: 3-stage cp.async pipeline, fp16 HMMA, fp32 accumulate ----
__global__ void __launch_bounds__(256, 3)
bitlinear_gemm(const float* __restrict__ bias, float* __restrict__ out) {
    extern __shared__ unsigned char smem[];
    const uint32_t sb = smem_u32(smem);
    const int tid = threadIdx.x;
    const int wid = tid >> 5;
    const int lid = tid & 31;
    const int warp_m = wid & 3;       // 4 warps along M (32 rows each)
    const int warp_n = wid >> 2;      // 2 warps along N (32 cols each)
    const int n0 = blockIdx.x * BN;   // grid.x = 8  (n fastest -> L2 reuse of x)
    const int m0 = blockIdx.y * BM;   // grid.y = 512

    if (tid < BN) {
        reinterpret_cast<float*>(smem + OFF_BIAS)[tid] = bias[n0 + tid];
    }

    // staging roles:
    //   A: thread -> (row = tid>>1, chunk pair cp = tid&1): 2 CP16 per buffer
    //   B: thread -> (row = tid>>2, chunk = tid&3): 1 CP16 per buffer
    const int arow = tid >> 1;
    const int acp  = tid & 1;
    const int brow = tid >> 2;
    const int bch  = tid & 3;
    const __half* ah_base = g_xhi + (size_t)(m0 + arow) * K_TOTAL + acp * 16;
    const __half* al_base = g_xlo + (size_t)(m0 + arow) * K_TOTAL + acp * 16;
    const __half* b_base  = g_ST  + (size_t)(n0 + brow) * K_TOTAL + bch * 8;
    const uint32_t asw0 = sw_off(arow, acp * 2 + 0);
    const uint32_t asw1 = sw_off(arow, acp * 2 + 1);
    const uint32_t bsw  = sw_off(brow, bch);

    auto issue_stage = [&](int kb) {
        if (kb < KB_STEPS) {
            const int buf = kb % STAGES;
            const __half* ah = ah_base + kb * BK;
            const __half* al = al_base + kb * BK;
            CP16(sb + OFF_AHI(buf) + asw0, ah);
            CP16(sb + OFF_AHI(buf) + asw1, ah + 8);
            CP16(sb + OFF_ALO(buf) + asw0, al);
            CP16(sb + OFF_ALO(buf) + asw1, al + 8);
            CP16(sb + OFF_BT(buf)  + bsw,  b_base + kb * BK);
        }
        CP_COMMIT();
    };

    issue_stage(0);
    issue_stage(1);

    float acc[2][4][4];
    #pragma unroll
    for (int i = 0; i < 2; i++)
        #pragma unroll
        for (int j = 0; j < 4; j++)
            #pragma unroll
            for (int c = 0; c < 4; c++) acc[i][j][c] = 0.0f;

    const int fr  = lid & 15;     // ldmatrix row within 16
    const int fch = lid >> 4;     // k-half select

    for (int kb = 0; kb < KB_STEPS; kb++) {
        CP_WAIT1();               // stage kb complete (1 newer group in flight)
        __syncthreads();          // stage kb-1 fully consumed by all warps
        issue_stage(kb + 2);      // refill buf (kb-1)%3 — safe post-barrier

        const int buf = kb % STAGES;
        const uint32_t ahi = sb + OFF_AHI(buf);
        const uint32_t alo = sb + OFF_ALO(buf);
        const uint32_t bsm = sb + OFF_BT(buf);

        #pragma unroll
        for (int ks = 0; ks < 2; ks++) {
            uint32_t a_hi[2][4], a_lo[2][4], bq[2][4];
            #pragma unroll
            for (int mt = 0; mt < 2; mt++) {
                int row = warp_m * 32 + mt * 16 + fr;
                uint32_t o = sw_off(row, ks * 2 + fch);
                LDSM_X4(a_hi[mt][0], a_hi[mt][1], a_hi[mt][2], a_hi[mt][3], ahi + o);
                LDSM_X4(a_lo[mt][0], a_lo[mt][1], a_lo[mt][2], a_lo[mt][3], alo + o);
            }
            #pragma unroll
            for (int p = 0; p < 2; p++) {   // 2 n-tiles per ldmatrix.x4
                int row = warp_n * 32 + p * 16 + fr;
                uint32_t o = sw_off(row, ks * 2 + fch);
                LDSM_X4(bq[p][0], bq[p][1], bq[p][2], bq[p][3], bsm + o);
            }
            #pragma unroll
            for (int mt = 0; mt < 2; mt++) {
                #pragma unroll
                for (int nt = 0; nt < 4; nt++) {
                    uint32_t b0 = bq[nt >> 1][nt & 1];
                    uint32_t b1 = bq[nt >> 1][2 + (nt & 1)];
                    MMA16816(acc[mt][nt], a_hi[mt][0], a_hi[mt][1], a_hi[mt][2], a_hi[mt][3], b0, b1);
                    MMA16816(acc[mt][nt], a_lo[mt][0], a_lo[mt][1], a_lo[mt][2], a_lo[mt][3], b0, b1);
                }
            }
        }
    }

    // ---- epilogue: scale by gamma, add bias, quantize, store ----
    const float gamma = g_gamma;
    const float* bias_s = reinterpret_cast<const float*>(smem + OFF_BIAS);
    #pragma unroll
    for (int mt = 0; mt < 2; mt++) {
        int row0 = m0 + warp_m * 32 + mt * 16 + (lid >> 2);
        #pragma unroll
        for (int nt = 0; nt < 4; nt++) {
            int coln = warp_n * 32 + nt * 8 + (lid & 3) * 2;
            float b0 = bias_s[coln], b1 = bias_s[coln + 1];
            float2 v0, v1;
            v0.x = quantize(acc[mt][nt][0] * gamma + b0);
            v0.y = quantize(acc[mt][nt][1] * gamma + b1);
            v1.x = quantize(acc[mt][nt][2] * gamma + b0);
            v1.y = quantize(acc[mt][nt][3] * gamma + b1);
            *reinterpret_cast<float2*>(out + (size_t)row0 * N_TOTAL + n0 + coln) = v0;
            *reinterpret_cast<float2*>(out + (size_t)(row0 + 8) * N_TOTAL + n0 + coln) = v1;
        }
    }
}

// ---- harness entry ----
extern "C" void kernel_launch(void* const* d_in, const int* in_sizes, int n_in,
                              void* d_out, int out_size) {
    const float* x    = (const float*)d_in[0];
    const float* w    = (const float*)d_in[1];
    const float* bias = (const float*)d_in[2];
    float* out = (float*)d_out;

    cudaFuncSetAttribute(bitlinear_gemm,
                         cudaFuncAttributeMaxDynamicSharedMemorySize, SMEM_TOTAL);

    reduce_rows<<<512, 256>>>(w);
    reduce_final<<<1, 256>>>();
    pack_signs<<<512, 512>>>(w);
    split_x<<<(M_TOTAL * K_TOTAL) / (8 * 256), 256>>>(x);

    dim3 grid(N_TOTAL / BN, M_TOTAL / BM);   // (8, 512): n fastest
    bitlinear_gemm<<<grid, 256, SMEM_TOTAL>>>(bias, out);
}